// round 14
// baseline (speedup 1.0000x reference)
#include <cuda_runtime.h>
#include <cuda_bf16.h>
#include <cstdint>
#include <math.h>

// ---------------- problem constants ----------------
#define BB   2
#define SS   2048
#define DIN  4096
#define DOUT 4096
#define NH   32
#define NKV  8
#define HD   128
#define GS   4          // NH / NKV
#define MM   (BB*SS)    // 4096 rows
#define NQKV (DOUT + 2 * NKV * HD)   // 6144 fused output cols
#define KOFF DOUT                    // K block offset in fused row
#define VOFF (DOUT + NKV * HD)       // V block offset

// ================= PTX helpers (base compute_103 ISA only) =================
__device__ __forceinline__ uint32_t smem_to_u32(const void* p) {
    uint32_t a;
    asm("{ .reg .u64 t; cvta.to.shared.u64 t, %1; cvt.u32.u64 %0, t; }" : "=r"(a) : "l"(p));
    return a;
}
#define CP_ASYNC16(dst, src) \
    asm volatile("cp.async.cg.shared.global [%0], [%1], 16;" :: "r"(dst), "l"(src))
#define CP_COMMIT()  asm volatile("cp.async.commit_group;" ::: "memory")
#define CP_WAIT(n)   asm volatile("cp.async.wait_group %0;" :: "n"(n) : "memory")

#define LDSM4(r0, r1, r2, r3, addr) \
    asm volatile("ldmatrix.sync.aligned.m8n8.x4.shared.b16 {%0,%1,%2,%3}, [%4];" \
                 : "=r"(r0), "=r"(r1), "=r"(r2), "=r"(r3) : "r"(addr))

#define MMA16816(c0, c1, c2, c3, a0, a1, a2, a3, b0, b1) \
    asm volatile("mma.sync.aligned.m16n8k16.row.col.f32.bf16.bf16.f32 " \
                 "{%0,%1,%2,%3}, {%4,%5,%6,%7}, {%8,%9}, {%0,%1,%2,%3};" \
                 : "+f"(c0), "+f"(c1), "+f"(c2), "+f"(c3) \
                 : "r"(a0), "r"(a1), "r"(a2), "r"(a3), "r"(b0), "r"(b1))

// packed fp32x2 (Blackwell base ISA, PTX 8.6+)
#define FMA2(acc, a, b) \
    asm("fma.rn.f32x2 %0, %1, %2, %0;" : "+l"(acc) : "l"(a), "l"(b))
#define MUL2(acc, b) \
    asm("mul.rn.f32x2 %0, %0, %1;" : "+l"(acc) : "l"(b))
__device__ __forceinline__ unsigned long long pack2(float v) {
    unsigned long long r; unsigned u = __float_as_uint(v);
    asm("mov.b64 %0, {%1, %1};" : "=l"(r) : "r"(u));
    return r;
}
__device__ __forceinline__ float pk_lo(unsigned long long v) {
    return __uint_as_float((unsigned)(v & 0xffffffffull));
}
__device__ __forceinline__ float pk_hi(unsigned long long v) {
    return __uint_as_float((unsigned)(v >> 32));
}
#define D2L(x) __double_as_longlong(x)

// ---------------- scratch (device globals) ----------
__device__ float g_QKV[(size_t)MM * NQKV];              // fused Q|K|V
__device__ float g_ctx[(size_t)MM * DOUT];
__device__ __nv_bfloat16 g_xb   [(size_t)MM   * 3 * DIN ];
__device__ __nv_bfloat16 g_Wqkvb[(size_t)NQKV * 3 * DIN ];   // fused weights
__device__ __nv_bfloat16 g_Wob  [(size_t)DOUT * 3 * DOUT];
__device__ __nv_bfloat16 g_ctxb [(size_t)MM   * 3 * DOUT];

// ============================================================================
// fp32 -> 3-segment bf16 split, row length C -> 3C.
// mode 0 (A operand): [h | h | l]      mode 1 (B operand): [h | l | h]
// ============================================================================
__global__ void split3_kernel(const float* __restrict__ in,
                              __nv_bfloat16* __restrict__ out,
                              int C, size_t total, int mode)
{
    size_t idx = (size_t)blockIdx.x * blockDim.x + threadIdx.x;
    if (idx >= total) return;
    size_t r = idx / (size_t)C;
    int    c = (int)(idx - r * C);
    float v = in[idx];
    __nv_bfloat16 h = __float2bfloat16(v);
    __nv_bfloat16 l = __float2bfloat16(v - __bfloat162float(h));
    __nv_bfloat16* o = out + r * (size_t)(3 * C);
    if (mode == 0) {            // A: [h | h | l]
        o[c]         = h;
        o[C + c]     = h;
        o[2 * C + c] = l;
    } else {                    // B: [h | l | h]
        o[c]         = h;
        o[C + c]     = l;
        o[2 * C + c] = h;
    }
}

// ============================================================================
// HMMA bf16 GEMM:  C[M,N] = A[M,K] * B[N,K]^T
// 128x128 CTA tile, BK=64 (halves barrier/wait count vs BK=32), 8 warps (2x4),
// warp tile 64x32, 3-stage cp.async pipeline, 2 CTAs/SM, single-buf frags.
// smem row stride = 144 B (9 chunks of 16B; 9r+c bijective mod 8 ->
// conflict-free ldmatrix).
// ============================================================================
#define ROWB   144
#define TILEB  (128 * ROWB)          // 18432 B per operand tile
#define STAGEB (2 * TILEB)           // 36864 B per stage (A then B)
#define NSTAGE 3
#define GSMEM  (NSTAGE * STAGEB)     // 110592 B  (<= 114688 at 2 CTAs/SM)

__global__ __launch_bounds__(256, 2) void gemm_hmma_kernel(
    const __nv_bfloat16* __restrict__ A, const __nv_bfloat16* __restrict__ B,
    float* __restrict__ C, int M, int N, int K)
{
    extern __shared__ __align__(1024) uint8_t sm_[];

    const int tid = threadIdx.x;
    const int wid = tid >> 5;
    const int l   = tid & 31;
    const int warp_m = wid >> 2;
    const int warp_n = wid & 3;

    int tm, tn;
    {
        int lin  = blockIdx.y * gridDim.x + blockIdx.x;
        int gsz  = 8 * gridDim.x;
        int gid  = lin / gsz;
        int rem  = lin - gid * gsz;
        int m0   = gid * 8;
        int msz  = min(8, (int)gridDim.y - m0);
        tm = m0 + rem % msz;
        tn = rem / msz;
    }
    const size_t row0 = (size_t)tm * 128;
    const size_t col0 = (size_t)tn * 128;

    const uint32_t sb = smem_to_u32(sm_);

    // staging: each tile is 128 rows x 128B (8 chunks); 1024 chunk-loads per
    // tile over 256 threads = 4 chunks/thread, as 4 consecutive 16B pieces.
    const int ldrow = tid >> 1;          // 0..127
    const int ldc0  = (tid & 1) * 4;     // chunk 0..3 or 4..7

    float acc[4][4][4];
#pragma unroll
    for (int i = 0; i < 4; i++)
#pragma unroll
        for (int j = 0; j < 4; j++)
#pragma unroll
            for (int q = 0; q < 4; q++) acc[i][j][q] = 0.f;

    const int nk = K >> 6;               // BK = 64 elements = 128 bytes

#define ISSUE_TILE(stg, t) do {                                                 \
    uint32_t ab = sb + (stg) * STAGEB;                                          \
    uint32_t bb = ab + TILEB;                                                   \
    const __nv_bfloat16* ap = A + (row0 + ldrow) * (size_t)K + (size_t)(t) * 64;\
    const __nv_bfloat16* bp = B + (col0 + ldrow) * (size_t)K + (size_t)(t) * 64;\
    _Pragma("unroll")                                                           \
    for (int u = 0; u < 4; u++) {                                               \
        uint32_t so = (uint32_t)(ldrow * ROWB + (ldc0 + u) * 16);               \
        CP_ASYNC16(ab + so, ap + (ldc0 + u) * 8);                               \
        CP_ASYNC16(bb + so, bp + (ldc0 + u) * 8);                               \
    } } while (0)

    // prologue: fill NSTAGE-1 stages
#pragma unroll
    for (int s = 0; s < NSTAGE - 1; s++) {
        if (s < nk) ISSUE_TILE(s, s);
        CP_COMMIT();
    }

    // lane-derived ldmatrix address components
    const int aRow = warp_m * 64 + (l & 15);
    const int aKof = (l >> 4) * 16;
    const int bRow = warp_n * 32 + ((l >> 4) & 1) * 8 + (l & 7);
    const int bKof = ((l >> 3) & 1) * 16;

    int stg = 0;
    for (int t = 0; t < nk; t++) {
        const uint32_t Ab = sb + stg * STAGEB;
        const uint32_t Bb = Ab + TILEB;

        CP_WAIT(NSTAGE - 2);
        __syncthreads();

        {
            int tf = t + NSTAGE - 1;
            if (tf < nk) {
                int sf = stg + NSTAGE - 1;
                if (sf >= NSTAGE) sf -= NSTAGE;
                ISSUE_TILE(sf, tf);
            }
            CP_COMMIT();
        }

        // ---- compute tile t: 4 k-steps of 16, single-buffered fragments ----
#pragma unroll
        for (int ks = 0; ks < 4; ks++) {
            uint32_t af[4][4], bf[4][2];
#pragma unroll
            for (int i = 0; i < 4; i++) {
                uint32_t ad = Ab + (uint32_t)((aRow + i * 16) * ROWB + ks * 32 + aKof);
                LDSM4(af[i][0], af[i][1], af[i][2], af[i][3], ad);
            }
#pragma unroll
            for (int j2 = 0; j2 < 2; j2++) {
                uint32_t bd = Bb + (uint32_t)((bRow + j2 * 16) * ROWB + ks * 32 + bKof);
                LDSM4(bf[2 * j2][0], bf[2 * j2][1], bf[2 * j2 + 1][0], bf[2 * j2 + 1][1], bd);
            }
#pragma unroll
            for (int i = 0; i < 4; i++)
#pragma unroll
                for (int j = 0; j < 4; j++)
                    MMA16816(acc[i][j][0], acc[i][j][1], acc[i][j][2], acc[i][j][3],
                             af[i][0], af[i][1], af[i][2], af[i][3],
                             bf[j][0], bf[j][1]);
        }
        if (++stg == NSTAGE) stg = 0;
    }
#undef ISSUE_TILE

    const int erow = (int)row0 + warp_m * 64 + (l >> 2);
    const int ecol = (int)col0 + warp_n * 32 + (l & 3) * 2;
#pragma unroll
    for (int i = 0; i < 4; i++) {
#pragma unroll
        for (int j = 0; j < 4; j++) {
            float* p0 = C + (size_t)(erow + i * 16)     * N + ecol + j * 8;
            float* p1 = C + (size_t)(erow + i * 16 + 8) * N + ecol + j * 8;
            *(float2*)p0 = make_float2(acc[i][j][0], acc[i][j][1]);
            *(float2*)p1 = make_float2(acc[i][j][2], acc[i][j][3]);
        }
    }
}

// ============================================================================
// RoPE (in place) on fused QKV buffer.
// ============================================================================
__global__ void rope_fused_kernel(float* __restrict__ QKV)
{
    size_t idx = (size_t)blockIdx.x * blockDim.x + threadIdx.x;
    size_t total = (size_t)BB * SS * (NH + NKV) * 64;
    if (idx >= total) return;

    int   i  = (int)(idx & 63);
    size_t t = idx >> 6;
    int   hh = (int)(t % (NH + NKV));
    size_t bs = t / (NH + NKV);
    int   s  = (int)(bs % SS);

    int coff = (hh < NH) ? hh * HD : KOFF + (hh - NH) * HD;
    float* p = QKV + bs * (size_t)NQKV + coff;

    float inv = 1.0f / powf(10000.0f, (float)(2 * i) / 128.0f);
    float ang = (float)s * inv;
    float sn, cs;
    sincosf(ang, &sn, &cs);

    float x1 = p[i];
    float x2 = p[i + 64];
    p[i]      = x1 * cs - x2 * sn;
    p[i + 64] = x2 * cs + x1 * sn;
}

// ============================================================================
// Causal flash attention (fp32, online softmax), register-blocked, f32x2.
// ============================================================================
#define SROW 36
#define ASMEM 77568

__global__ __launch_bounds__(256) void attn_kernel(
    const float* __restrict__ QKV, float* __restrict__ ctx)
{
    extern __shared__ float sm[];
    float* Qs  = sm;                        // 64*132
    float* Ks  = Qs + 64 * 132;             // 32*132
    float* Vs  = Ks + 32 * 132;             // 32*132
    float* Ssm = Vs + 32 * 132;             // 64*SROW
    float* msh = Ssm + 64 * SROW;           // 64
    float* lsh = msh + 64;                  // 64
    float* ash = lsh + 64;                  // 64

    const int q0  = blockIdx.x * 64;
    const int h   = blockIdx.y;
    const int b   = blockIdx.z;
    const int g   = h / GS;
    const int tid = threadIdx.x;

    const int sr0 = (tid >> 4) * 4;         // QK: 4 rows
    const int sc0 = (tid & 15) * 2;         //     2 cols
    const int xrow = tid >> 2;              // softmax: 4 lanes/row
    const int xq   = tid & 3;
    const int pr0 = (tid >> 3) * 2;         // PV: 2 rows
    const int pc0 = (tid & 7) * 16;         //     16 cols

    const float* Qb = QKV + ((size_t)(b * SS + q0)) * NQKV + (size_t)h * HD;
#pragma unroll
    for (int u = 0; u < 8; u++) {
        int i  = tid + u * 256;
        int r  = i >> 5;
        int c4 = i & 31;
        ((float4*)(Qs + r * 132))[c4] = ((const float4*)(Qb + (size_t)r * NQKV))[c4];
    }
    if (tid < 64) { msh[tid] = -1e30f; lsh[tid] = 0.f; }

    unsigned long long o_pk[2][8];
#pragma unroll
    for (int r = 0; r < 2; r++)
#pragma unroll
        for (int c = 0; c < 8; c++) o_pk[r][c] = 0ull;

    const float scale = 0.08838834764831845f;
    const int kmax = q0 + 64;

    for (int j0 = 0; j0 < kmax; j0 += 32) {
        __syncthreads();

        const float* Kb = QKV + ((size_t)(b * SS + j0)) * NQKV + KOFF + (size_t)g * HD;
        const float* Vb = QKV + ((size_t)(b * SS + j0)) * NQKV + VOFF + (size_t)g * HD;
#pragma unroll
        for (int u = 0; u < 4; u++) {
            int i  = tid + u * 256;
            int r  = i >> 5;
            int c4 = i & 31;
            ((float4*)(Ks + r * 132))[c4] = ((const float4*)(Kb + (size_t)r * NQKV))[c4];
            ((float4*)(Vs + r * 132))[c4] = ((const float4*)(Vb + (size_t)r * NQKV))[c4];
        }
        __syncthreads();

        // scores: 4x2 register block, packed f32x2 accumulation
        {
            unsigned long long s_pk[4][2];
#pragma unroll
            for (int r = 0; r < 4; r++) { s_pk[r][0] = 0ull; s_pk[r][1] = 0ull; }
            const double2* k0p = (const double2*)(Ks + sc0 * 132);
            const double2* k1p = (const double2*)(Ks + (sc0 + 1) * 132);
#pragma unroll
            for (int k4 = 0; k4 < 32; k4++) {
                double2 kv0 = k0p[k4];
                double2 kv1 = k1p[k4];
                unsigned long long k0a = D2L(kv0.x), k0b = D2L(kv0.y);
                unsigned long long k1a = D2L(kv1.x), k1b = D2L(kv1.y);
#pragma unroll
                for (int r = 0; r < 4; r++) {
                    double2 qv = ((const double2*)(Qs + (sr0 + r) * 132))[k4];
                    unsigned long long qa = D2L(qv.x), qb = D2L(qv.y);
                    FMA2(s_pk[r][0], qa, k0a);
                    FMA2(s_pk[r][0], qb, k0b);
                    FMA2(s_pk[r][1], qa, k1a);
                    FMA2(s_pk[r][1], qb, k1b);
                }
            }
            const bool diag = (j0 + 31 > q0);
#pragma unroll
            for (int r = 0; r < 4; r++) {
#pragma unroll
                for (int c = 0; c < 2; c++) {
                    float v = (pk_lo(s_pk[r][c]) + pk_hi(s_pk[r][c])) * scale;
                    if (diag && (j0 + sc0 + c > q0 + sr0 + r)) v = -1e30f;
                    Ssm[(sr0 + r) * SROW + sc0 + c] = v;
                }
            }
        }
        __syncthreads();

        // online softmax: 4 lanes/row, 8 cols each
        {
            float* srow = Ssm + xrow * SROW + xq * 8;
            float mt = -1e30f;
#pragma unroll
            for (int jj = 0; jj < 8; jj++) mt = fmaxf(mt, srow[jj]);
            mt = fmaxf(mt, __shfl_xor_sync(0xffffffffu, mt, 1));
            mt = fmaxf(mt, __shfl_xor_sync(0xffffffffu, mt, 2));
            float m_old = msh[xrow];
            float m_new = fmaxf(m_old, mt);
            float alpha = expf(m_old - m_new);
            float lsum = 0.f;
#pragma unroll
            for (int jj = 0; jj < 8; jj++) {
                float p = expf(srow[jj] - m_new);
                srow[jj] = p;
                lsum += p;
            }
            lsum += __shfl_xor_sync(0xffffffffu, lsum, 1);
            lsum += __shfl_xor_sync(0xffffffffu, lsum, 2);
            if (xq == 0) {
                msh[xrow] = m_new;
                lsh[xrow] = lsh[xrow] * alpha + lsum;
                ash[xrow] = alpha;
            }
        }
        __syncthreads();

        // PV: 2 rows x 16 cols per thread, packed f32x2
        {
            unsigned long long apk0 = pack2(ash[pr0]);
            unsigned long long apk1 = pack2(ash[pr0 + 1]);
#pragma unroll
            for (int c = 0; c < 8; c++) {
                MUL2(o_pk[0][c], apk0);
                MUL2(o_pk[1][c], apk1);
            }
            const float* p0r = Ssm + pr0 * SROW;
            const float* p1r = Ssm + (pr0 + 1) * SROW;
#pragma unroll
            for (int j = 0; j < 32; j++) {
                unsigned long long ppk0 = pack2(p0r[j]);
                unsigned long long ppk1 = pack2(p1r[j]);
                const double2* vp = (const double2*)(Vs + j * 132 + pc0);
#pragma unroll
                for (int c = 0; c < 4; c++) {
                    double2 vv = vp[c];
                    unsigned long long va = D2L(vv.x), vb = D2L(vv.y);
                    FMA2(o_pk[0][2 * c],     ppk0, va);
                    FMA2(o_pk[0][2 * c + 1], ppk0, vb);
                    FMA2(o_pk[1][2 * c],     ppk1, va);
                    FMA2(o_pk[1][2 * c + 1], ppk1, vb);
                }
            }
        }
    }

    // epilogue: unpack, normalize, write ctx
#pragma unroll
    for (int r = 0; r < 2; r++) {
        float inv_l = 1.f / lsh[pr0 + r];
        float* outp = ctx + ((size_t)(b * SS + q0 + pr0 + r)) * DOUT + (size_t)h * HD + pc0;
#pragma unroll
        for (int c = 0; c < 4; c++) {
            float4 v;
            v.x = pk_lo(o_pk[r][2 * c])     * inv_l;
            v.y = pk_hi(o_pk[r][2 * c])     * inv_l;
            v.z = pk_lo(o_pk[r][2 * c + 1]) * inv_l;
            v.w = pk_hi(o_pk[r][2 * c + 1]) * inv_l;
            ((float4*)outp)[c] = v;
        }
    }
}

// ============================================================================
// launch  (Wo split moved BEFORE the QKV gemm so ncu -s 5 captures the gemm)
// ============================================================================
extern "C" void kernel_launch(void* const* d_in, const int* in_sizes, int n_in,
                              void* d_out, int out_size)
{
    const float* x  = (const float*)d_in[0];
    const float* Wq = (const float*)d_in[1];
    const float* Wk = (const float*)d_in[2];
    const float* Wv = (const float*)d_in[3];
    const float* Wo = (const float*)d_in[4];
    float* out = (float*)d_out;

    float *QKVp, *Cp;
    __nv_bfloat16 *xb, *Wqkvb, *Wob, *ctxb;
    cudaGetSymbolAddress((void**)&QKVp, g_QKV);
    cudaGetSymbolAddress((void**)&Cp, g_ctx);
    cudaGetSymbolAddress((void**)&xb, g_xb);
    cudaGetSymbolAddress((void**)&Wqkvb, g_Wqkvb);
    cudaGetSymbolAddress((void**)&Wob, g_Wob);
    cudaGetSymbolAddress((void**)&ctxb, g_ctxb);

    cudaFuncSetAttribute(attn_kernel,
                         cudaFuncAttributeMaxDynamicSharedMemorySize, ASMEM);
    cudaFuncSetAttribute(gemm_hmma_kernel,
                         cudaFuncAttributeMaxDynamicSharedMemorySize, GSMEM);

    // splits (#0..#4): x, Wq, Wk, Wv, Wo
    size_t t1 = (size_t)MM * DIN;
    split3_kernel<<<(unsigned)((t1 + 255) / 256), 256>>>(x, xb, DIN, t1, 0);
    size_t t2 = (size_t)DOUT * DIN;
    split3_kernel<<<(unsigned)((t2 + 255) / 256), 256>>>(Wq, Wqkvb, DIN, t2, 1);
    size_t t3 = (size_t)(NKV * HD) * DIN;
    split3_kernel<<<(unsigned)((t3 + 255) / 256), 256>>>(
        Wk, Wqkvb + (size_t)KOFF * 3 * DIN, DIN, t3, 1);
    split3_kernel<<<(unsigned)((t3 + 255) / 256), 256>>>(
        Wv, Wqkvb + (size_t)VOFF * 3 * DIN, DIN, t3, 1);
    size_t t4 = (size_t)DOUT * DOUT;
    split3_kernel<<<(unsigned)((t4 + 255) / 256), 256>>>(Wo, Wob, DOUT, t4, 1);

    // #5: fused QKV projection GEMM (ncu -s 5 captures this)
    {
        dim3 gq(NQKV / 128, MM / 128);
        gemm_hmma_kernel<<<gq, 256, GSMEM>>>(xb, Wqkvb, QKVp, MM, NQKV, 3 * DIN);
    }

    // RoPE on Q and K heads
    {
        size_t tr = (size_t)BB * SS * (NH + NKV) * 64;
        rope_fused_kernel<<<(unsigned)((tr + 255) / 256), 256>>>(QKVp);
    }

    // attention
    {
        dim3 ga(SS / 64, NH, BB);
        attn_kernel<<<ga, 256, ASMEM>>>(QKVp, Cp);
    }

    // output projection -> d_out
    {
        size_t t5 = (size_t)MM * DOUT;
        split3_kernel<<<(unsigned)((t5 + 255) / 256), 256>>>(Cp, ctxb, DOUT, t5, 0);
        dim3 go(DOUT / 128, MM / 128);
        gemm_hmma_kernel<<<go, 256, GSMEM>>>(ctxb, Wob, out, MM, DOUT, 3 * DOUT);
    }
}

// round 16
// speedup vs baseline: 1.1421x; 1.1421x over previous
#include <cuda_runtime.h>
#include <cuda_bf16.h>
#include <cstdint>
#include <math.h>

// ---------------- problem constants ----------------
#define BB   2
#define SS   2048
#define DIN  4096
#define DOUT 4096
#define NH   32
#define NKV  8
#define HD   128
#define GS   4          // NH / NKV
#define MM   (BB*SS)    // 4096 rows
#define NQKV (DOUT + 2 * NKV * HD)   // 6144 fused output cols
#define KOFF DOUT
#define VOFF (DOUT + NKV * HD)

// ================= PTX helpers (base compute_103 ISA only) =================
__device__ __forceinline__ uint32_t smem_to_u32(const void* p) {
    uint32_t a;
    asm("{ .reg .u64 t; cvta.to.shared.u64 t, %1; cvt.u32.u64 %0, t; }" : "=r"(a) : "l"(p));
    return a;
}
#define CP_ASYNC16(dst, src) \
    asm volatile("cp.async.cg.shared.global [%0], [%1], 16;" :: "r"(dst), "l"(src))
#define CP_COMMIT()  asm volatile("cp.async.commit_group;" ::: "memory")
#define CP_WAIT(n)   asm volatile("cp.async.wait_group %0;" :: "n"(n) : "memory")

#define LDSM4(r0, r1, r2, r3, addr) \
    asm volatile("ldmatrix.sync.aligned.m8n8.x4.shared.b16 {%0,%1,%2,%3}, [%4];" \
                 : "=r"(r0), "=r"(r1), "=r"(r2), "=r"(r3) : "r"(addr))

#define MMA16816(c0, c1, c2, c3, a0, a1, a2, a3, b0, b1) \
    asm volatile("mma.sync.aligned.m16n8k16.row.col.f32.bf16.bf16.f32 " \
                 "{%0,%1,%2,%3}, {%4,%5,%6,%7}, {%8,%9}, {%0,%1,%2,%3};" \
                 : "+f"(c0), "+f"(c1), "+f"(c2), "+f"(c3) \
                 : "r"(a0), "r"(a1), "r"(a2), "r"(a3), "r"(b0), "r"(b1))

// packed fp32x2 (Blackwell base ISA, PTX 8.6+)
#define FMA2(acc, a, b) \
    asm("fma.rn.f32x2 %0, %1, %2, %0;" : "+l"(acc) : "l"(a), "l"(b))
#define MUL2(acc, b) \
    asm("mul.rn.f32x2 %0, %0, %1;" : "+l"(acc) : "l"(b))
__device__ __forceinline__ unsigned long long pack2(float v) {
    unsigned long long r; unsigned u = __float_as_uint(v);
    asm("mov.b64 %0, {%1, %1};" : "=l"(r) : "r"(u));
    return r;
}
__device__ __forceinline__ float pk_lo(unsigned long long v) {
    return __uint_as_float((unsigned)(v & 0xffffffffull));
}
__device__ __forceinline__ float pk_hi(unsigned long long v) {
    return __uint_as_float((unsigned)(v >> 32));
}
#define D2L(x) __double_as_longlong(x)

// ---------------- scratch (device globals) ----------
__device__ float g_QKV[(size_t)MM * NQKV];
__device__ float g_ctx[(size_t)MM * DOUT];
__device__ __nv_bfloat16 g_xb   [(size_t)MM   * 3 * DIN ];
__device__ __nv_bfloat16 g_Wqkvb[(size_t)NQKV * 3 * DIN ];
__device__ __nv_bfloat16 g_Wob  [(size_t)DOUT * 3 * DOUT];
__device__ __nv_bfloat16 g_ctxb [(size_t)MM   * 3 * DOUT];

// ============================================================================
// fp32 -> 3-segment bf16 split.  mode 0: [h|h|l]  mode 1: [h|l|h]
// ============================================================================
__global__ void split3_kernel(const float* __restrict__ in,
                              __nv_bfloat16* __restrict__ out,
                              int C, size_t total, int mode)
{
    size_t idx = (size_t)blockIdx.x * blockDim.x + threadIdx.x;
    if (idx >= total) return;
    size_t r = idx / (size_t)C;
    int    c = (int)(idx - r * C);
    float v = in[idx];
    __nv_bfloat16 h = __float2bfloat16(v);
    __nv_bfloat16 l = __float2bfloat16(v - __bfloat162float(h));
    __nv_bfloat16* o = out + r * (size_t)(3 * C);
    if (mode == 0) { o[c] = h; o[C + c] = h; o[2 * C + c] = l; }
    else           { o[c] = h; o[C + c] = l; o[2 * C + c] = h; }
}

// ============================================================================
// HMMA bf16 GEMM:  C[M,N] = A[M,K] * B[N,K]^T
// 128x128 CTA tile, BK=32, 4 warps (2x2), warp tile 64x64,
// 4-stage cp.async pipeline, 2 CTAs/SM, single-buffered fragments.
// LDSM traffic 32KB/iter (vs 48KB with 8x(64x32)) -> tensor-bound.
// smem row stride = 80 B (conflict-free ldmatrix).
// ============================================================================
#define ROWB   80
#define TILEB  (128 * ROWB)          // 10240 B per operand tile
#define STAGEB (2 * TILEB)           // 20480 B per stage
#define NSTAGE 4
#define GSMEM  (NSTAGE * STAGEB)     // 81920 B

__global__ __launch_bounds__(128, 2) void gemm_hmma_kernel(
    const __nv_bfloat16* __restrict__ A, const __nv_bfloat16* __restrict__ B,
    float* __restrict__ C, int M, int N, int K)
{
    extern __shared__ __align__(1024) uint8_t sm_[];

    const int tid = threadIdx.x;
    const int wid = tid >> 5;
    const int l   = tid & 31;
    const int warp_m = wid >> 1;         // 0..1
    const int warp_n = wid & 1;          // 0..1

    // CTA swizzle: group 8 M-tiles per N column for L2 reuse of B
    int tm, tn;
    {
        int lin  = blockIdx.y * gridDim.x + blockIdx.x;
        int gsz  = 8 * gridDim.x;
        int gid  = lin / gsz;
        int rem  = lin - gid * gsz;
        int m0   = gid * 8;
        int msz  = min(8, (int)gridDim.y - m0);
        tm = m0 + rem % msz;
        tn = rem / msz;
    }
    const size_t row0 = (size_t)tm * 128;
    const size_t col0 = (size_t)tn * 128;

    const uint32_t sb = smem_to_u32(sm_);

    float acc[4][8][4];
#pragma unroll
    for (int i = 0; i < 4; i++)
#pragma unroll
        for (int j = 0; j < 8; j++)
#pragma unroll
            for (int q = 0; q < 4; q++) acc[i][j][q] = 0.f;

    const int nk = K >> 5;

    // staging: 128 threads, 4 passes each for A and B: i = tid + u*128,
    // row = i>>2 (0..127), chunk = i&3 (16B units of the 64B row)
#define ISSUE_TILE(stg, t) do {                                                 \
    uint32_t ab = sb + (stg) * STAGEB;                                          \
    uint32_t bb = ab + TILEB;                                                   \
    _Pragma("unroll")                                                           \
    for (int u = 0; u < 4; u++) {                                               \
        int i = tid + u * 128;                                                  \
        int r = i >> 2;                                                         \
        int c = i & 3;                                                          \
        uint32_t so = (uint32_t)(r * ROWB + c * 16);                            \
        CP_ASYNC16(ab + so,                                                     \
                   A + (row0 + r) * (size_t)K + (size_t)(t) * 32 + c * 8);      \
        CP_ASYNC16(bb + so,                                                     \
                   B + (col0 + r) * (size_t)K + (size_t)(t) * 32 + c * 8);      \
    } } while (0)

    // prologue: fill NSTAGE-1 stages
#pragma unroll
    for (int s = 0; s < NSTAGE - 1; s++) {
        if (s < nk) ISSUE_TILE(s, s);
        CP_COMMIT();
    }

    // lane-derived ldmatrix address components (verified mapping)
    const int aRow = warp_m * 64 + (l & 15);                       // + i*16
    const int aKof = (l >> 4) * 16;                                // bytes
    const int bRow = warp_n * 64 + ((l >> 4) & 1) * 8 + (l & 7);   // + j2*16
    const int bKof = ((l >> 3) & 1) * 16;                          // bytes

    for (int t = 0; t < nk; t++) {
        const int stg = t & (NSTAGE - 1);
        const uint32_t Ab = sb + stg * STAGEB;
        const uint32_t Bb = Ab + TILEB;

        CP_WAIT(NSTAGE - 2);          // tile t resident
        __syncthreads();              // all warps done with the slot we refill

        {   // refill the slot freed last iteration
            int tf = t + NSTAGE - 1;
            if (tf < nk) ISSUE_TILE((tf & (NSTAGE - 1)), tf);
            CP_COMMIT();
        }

        // ---- compute tile t, single-buffered fragments ----
#pragma unroll
        for (int ks = 0; ks < 2; ks++) {
            uint32_t af[4][4], bf[8][2];
#pragma unroll
            for (int i = 0; i < 4; i++) {
                uint32_t ad = Ab + (uint32_t)((aRow + i * 16) * ROWB + ks * 32 + aKof);
                LDSM4(af[i][0], af[i][1], af[i][2], af[i][3], ad);
            }
#pragma unroll
            for (int j2 = 0; j2 < 4; j2++) {
                uint32_t bd = Bb + (uint32_t)((bRow + j2 * 16) * ROWB + ks * 32 + bKof);
                LDSM4(bf[2 * j2][0], bf[2 * j2][1], bf[2 * j2 + 1][0], bf[2 * j2 + 1][1], bd);
            }
#pragma unroll
            for (int i = 0; i < 4; i++)
#pragma unroll
                for (int j = 0; j < 8; j++)
                    MMA16816(acc[i][j][0], acc[i][j][1], acc[i][j][2], acc[i][j][3],
                             af[i][0], af[i][1], af[i][2], af[i][3],
                             bf[j][0], bf[j][1]);
        }
    }
#undef ISSUE_TILE

    // epilogue
    const int erow = (int)row0 + warp_m * 64 + (l >> 2);
    const int ecol = (int)col0 + warp_n * 64 + (l & 3) * 2;
#pragma unroll
    for (int i = 0; i < 4; i++) {
#pragma unroll
        for (int j = 0; j < 8; j++) {
            float* p0 = C + (size_t)(erow + i * 16)     * N + ecol + j * 8;
            float* p1 = C + (size_t)(erow + i * 16 + 8) * N + ecol + j * 8;
            *(float2*)p0 = make_float2(acc[i][j][0], acc[i][j][1]);
            *(float2*)p1 = make_float2(acc[i][j][2], acc[i][j][3]);
        }
    }
}

// ============================================================================
// RoPE (in place) on fused QKV buffer.
// ============================================================================
__global__ void rope_fused_kernel(float* __restrict__ QKV)
{
    size_t idx = (size_t)blockIdx.x * blockDim.x + threadIdx.x;
    size_t total = (size_t)BB * SS * (NH + NKV) * 64;
    if (idx >= total) return;

    int   i  = (int)(idx & 63);
    size_t t = idx >> 6;
    int   hh = (int)(t % (NH + NKV));
    size_t bs = t / (NH + NKV);
    int   s  = (int)(bs % SS);

    int coff = (hh < NH) ? hh * HD : KOFF + (hh - NH) * HD;
    float* p = QKV + bs * (size_t)NQKV + coff;

    float inv = 1.0f / powf(10000.0f, (float)(2 * i) / 128.0f);
    float ang = (float)s * inv;
    float sn, cs;
    sincosf(ang, &sn, &cs);

    float x1 = p[i];
    float x2 = p[i + 64];
    p[i]      = x1 * cs - x2 * sn;
    p[i + 64] = x2 * cs + x1 * sn;
}

// ============================================================================
// Causal flash attention (fp32, online softmax), register-blocked, f32x2.
// ============================================================================
#define SROW 36
#define ASMEM 77568

__global__ __launch_bounds__(256) void attn_kernel(
    const float* __restrict__ QKV, float* __restrict__ ctx)
{
    extern __shared__ float sm[];
    float* Qs  = sm;
    float* Ks  = Qs + 64 * 132;
    float* Vs  = Ks + 32 * 132;
    float* Ssm = Vs + 32 * 132;
    float* msh = Ssm + 64 * SROW;
    float* lsh = msh + 64;
    float* ash = lsh + 64;

    const int q0  = blockIdx.x * 64;
    const int h   = blockIdx.y;
    const int b   = blockIdx.z;
    const int g   = h / GS;
    const int tid = threadIdx.x;

    const int sr0 = (tid >> 4) * 4;
    const int sc0 = (tid & 15) * 2;
    const int xrow = tid >> 2;
    const int xq   = tid & 3;
    const int pr0 = (tid >> 3) * 2;
    const int pc0 = (tid & 7) * 16;

    const float* Qb = QKV + ((size_t)(b * SS + q0)) * NQKV + (size_t)h * HD;
#pragma unroll
    for (int u = 0; u < 8; u++) {
        int i  = tid + u * 256;
        int r  = i >> 5;
        int c4 = i & 31;
        ((float4*)(Qs + r * 132))[c4] = ((const float4*)(Qb + (size_t)r * NQKV))[c4];
    }
    if (tid < 64) { msh[tid] = -1e30f; lsh[tid] = 0.f; }

    unsigned long long o_pk[2][8];
#pragma unroll
    for (int r = 0; r < 2; r++)
#pragma unroll
        for (int c = 0; c < 8; c++) o_pk[r][c] = 0ull;

    const float scale = 0.08838834764831845f;
    const int kmax = q0 + 64;

    for (int j0 = 0; j0 < kmax; j0 += 32) {
        __syncthreads();

        const float* Kb = QKV + ((size_t)(b * SS + j0)) * NQKV + KOFF + (size_t)g * HD;
        const float* Vb = QKV + ((size_t)(b * SS + j0)) * NQKV + VOFF + (size_t)g * HD;
#pragma unroll
        for (int u = 0; u < 4; u++) {
            int i  = tid + u * 256;
            int r  = i >> 5;
            int c4 = i & 31;
            ((float4*)(Ks + r * 132))[c4] = ((const float4*)(Kb + (size_t)r * NQKV))[c4];
            ((float4*)(Vs + r * 132))[c4] = ((const float4*)(Vb + (size_t)r * NQKV))[c4];
        }
        __syncthreads();

        {
            unsigned long long s_pk[4][2];
#pragma unroll
            for (int r = 0; r < 4; r++) { s_pk[r][0] = 0ull; s_pk[r][1] = 0ull; }
            const double2* k0p = (const double2*)(Ks + sc0 * 132);
            const double2* k1p = (const double2*)(Ks + (sc0 + 1) * 132);
#pragma unroll
            for (int k4 = 0; k4 < 32; k4++) {
                double2 kv0 = k0p[k4];
                double2 kv1 = k1p[k4];
                unsigned long long k0a = D2L(kv0.x), k0b = D2L(kv0.y);
                unsigned long long k1a = D2L(kv1.x), k1b = D2L(kv1.y);
#pragma unroll
                for (int r = 0; r < 4; r++) {
                    double2 qv = ((const double2*)(Qs + (sr0 + r) * 132))[k4];
                    unsigned long long qa = D2L(qv.x), qb = D2L(qv.y);
                    FMA2(s_pk[r][0], qa, k0a);
                    FMA2(s_pk[r][0], qb, k0b);
                    FMA2(s_pk[r][1], qa, k1a);
                    FMA2(s_pk[r][1], qb, k1b);
                }
            }
            const bool diag = (j0 + 31 > q0);
#pragma unroll
            for (int r = 0; r < 4; r++) {
#pragma unroll
                for (int c = 0; c < 2; c++) {
                    float v = (pk_lo(s_pk[r][c]) + pk_hi(s_pk[r][c])) * scale;
                    if (diag && (j0 + sc0 + c > q0 + sr0 + r)) v = -1e30f;
                    Ssm[(sr0 + r) * SROW + sc0 + c] = v;
                }
            }
        }
        __syncthreads();

        {
            float* srow = Ssm + xrow * SROW + xq * 8;
            float mt = -1e30f;
#pragma unroll
            for (int jj = 0; jj < 8; jj++) mt = fmaxf(mt, srow[jj]);
            mt = fmaxf(mt, __shfl_xor_sync(0xffffffffu, mt, 1));
            mt = fmaxf(mt, __shfl_xor_sync(0xffffffffu, mt, 2));
            float m_old = msh[xrow];
            float m_new = fmaxf(m_old, mt);
            float alpha = expf(m_old - m_new);
            float lsum = 0.f;
#pragma unroll
            for (int jj = 0; jj < 8; jj++) {
                float p = expf(srow[jj] - m_new);
                srow[jj] = p;
                lsum += p;
            }
            lsum += __shfl_xor_sync(0xffffffffu, lsum, 1);
            lsum += __shfl_xor_sync(0xffffffffu, lsum, 2);
            if (xq == 0) {
                msh[xrow] = m_new;
                lsh[xrow] = lsh[xrow] * alpha + lsum;
                ash[xrow] = alpha;
            }
        }
        __syncthreads();

        {
            unsigned long long apk0 = pack2(ash[pr0]);
            unsigned long long apk1 = pack2(ash[pr0 + 1]);
#pragma unroll
            for (int c = 0; c < 8; c++) {
                MUL2(o_pk[0][c], apk0);
                MUL2(o_pk[1][c], apk1);
            }
            const float* p0r = Ssm + pr0 * SROW;
            const float* p1r = Ssm + (pr0 + 1) * SROW;
#pragma unroll
            for (int j = 0; j < 32; j++) {
                unsigned long long ppk0 = pack2(p0r[j]);
                unsigned long long ppk1 = pack2(p1r[j]);
                const double2* vp = (const double2*)(Vs + j * 132 + pc0);
#pragma unroll
                for (int c = 0; c < 4; c++) {
                    double2 vv = vp[c];
                    unsigned long long va = D2L(vv.x), vb = D2L(vv.y);
                    FMA2(o_pk[0][2 * c],     ppk0, va);
                    FMA2(o_pk[0][2 * c + 1], ppk0, vb);
                    FMA2(o_pk[1][2 * c],     ppk1, va);
                    FMA2(o_pk[1][2 * c + 1], ppk1, vb);
                }
            }
        }
    }

#pragma unroll
    for (int r = 0; r < 2; r++) {
        float inv_l = 1.f / lsh[pr0 + r];
        float* outp = ctx + ((size_t)(b * SS + q0 + pr0 + r)) * DOUT + (size_t)h * HD + pc0;
#pragma unroll
        for (int c = 0; c < 4; c++) {
            float4 v;
            v.x = pk_lo(o_pk[r][2 * c])     * inv_l;
            v.y = pk_hi(o_pk[r][2 * c])     * inv_l;
            v.z = pk_lo(o_pk[r][2 * c + 1]) * inv_l;
            v.w = pk_hi(o_pk[r][2 * c + 1]) * inv_l;
            ((float4*)outp)[c] = v;
        }
    }
}

// ============================================================================
// launch
// ============================================================================
extern "C" void kernel_launch(void* const* d_in, const int* in_sizes, int n_in,
                              void* d_out, int out_size)
{
    const float* x  = (const float*)d_in[0];
    const float* Wq = (const float*)d_in[1];
    const float* Wk = (const float*)d_in[2];
    const float* Wv = (const float*)d_in[3];
    const float* Wo = (const float*)d_in[4];
    float* out = (float*)d_out;

    float *QKVp, *Cp;
    __nv_bfloat16 *xb, *Wqkvb, *Wob, *ctxb;
    cudaGetSymbolAddress((void**)&QKVp, g_QKV);
    cudaGetSymbolAddress((void**)&Cp, g_ctx);
    cudaGetSymbolAddress((void**)&xb, g_xb);
    cudaGetSymbolAddress((void**)&Wqkvb, g_Wqkvb);
    cudaGetSymbolAddress((void**)&Wob, g_Wob);
    cudaGetSymbolAddress((void**)&ctxb, g_ctxb);

    cudaFuncSetAttribute(attn_kernel,
                         cudaFuncAttributeMaxDynamicSharedMemorySize, ASMEM);
    cudaFuncSetAttribute(gemm_hmma_kernel,
                         cudaFuncAttributeMaxDynamicSharedMemorySize, GSMEM);

    // splits: x, Wq, Wk, Wv, Wo
    size_t t1 = (size_t)MM * DIN;
    split3_kernel<<<(unsigned)((t1 + 255) / 256), 256>>>(x, xb, DIN, t1, 0);
    size_t t2 = (size_t)DOUT * DIN;
    split3_kernel<<<(unsigned)((t2 + 255) / 256), 256>>>(Wq, Wqkvb, DIN, t2, 1);
    size_t t3 = (size_t)(NKV * HD) * DIN;
    split3_kernel<<<(unsigned)((t3 + 255) / 256), 256>>>(
        Wk, Wqkvb + (size_t)KOFF * 3 * DIN, DIN, t3, 1);
    split3_kernel<<<(unsigned)((t3 + 255) / 256), 256>>>(
        Wv, Wqkvb + (size_t)VOFF * 3 * DIN, DIN, t3, 1);
    size_t t4 = (size_t)DOUT * DOUT;
    split3_kernel<<<(unsigned)((t4 + 255) / 256), 256>>>(Wo, Wob, DOUT, t4, 1);

    // fused QKV projection GEMM
    {
        dim3 gq(NQKV / 128, MM / 128);
        gemm_hmma_kernel<<<gq, 128, GSMEM>>>(xb, Wqkvb, QKVp, MM, NQKV, 3 * DIN);
    }

    // RoPE on Q and K heads
    {
        size_t tr = (size_t)BB * SS * (NH + NKV) * 64;
        rope_fused_kernel<<<(unsigned)((tr + 255) / 256), 256>>>(QKVp);
    }

    // attention
    {
        dim3 ga(SS / 64, NH, BB);
        attn_kernel<<<ga, 256, ASMEM>>>(QKVp, Cp);
    }

    // output projection -> d_out
    {
        size_t t5 = (size_t)MM * DOUT;
        split3_kernel<<<(unsigned)((t5 + 255) / 256), 256>>>(Cp, ctxb, DOUT, t5, 0);
        dim3 go(DOUT / 128, MM / 128);
        gemm_hmma_kernel<<<go, 128, GSMEM>>>(ctxb, Wob, out, MM, DOUT, 3 * DOUT);
    }
}

// round 17
// speedup vs baseline: 1.1597x; 1.0154x over previous
#include <cuda_runtime.h>
#include <cuda_bf16.h>
#include <cstdint>
#include <math.h>

// ---------------- problem constants ----------------
#define BB   2
#define SS   2048
#define DIN  4096
#define DOUT 4096
#define NH   32
#define NKV  8
#define HD   128
#define GS   4          // NH / NKV
#define MM   (BB*SS)    // 4096 rows
#define NQKV (DOUT + 2 * NKV * HD)   // 6144 fused output cols
#define KOFF DOUT
#define VOFF (DOUT + NKV * HD)

// ================= PTX helpers (base compute_103 ISA only) =================
__device__ __forceinline__ uint32_t smem_to_u32(const void* p) {
    uint32_t a;
    asm("{ .reg .u64 t; cvta.to.shared.u64 t, %1; cvt.u32.u64 %0, t; }" : "=r"(a) : "l"(p));
    return a;
}
#define CP_ASYNC16(dst, src) \
    asm volatile("cp.async.cg.shared.global [%0], [%1], 16;" :: "r"(dst), "l"(src))
#define CP_COMMIT()  asm volatile("cp.async.commit_group;" ::: "memory")
#define CP_WAIT(n)   asm volatile("cp.async.wait_group %0;" :: "n"(n) : "memory")

#define LDSM4(r0, r1, r2, r3, addr) \
    asm volatile("ldmatrix.sync.aligned.m8n8.x4.shared.b16 {%0,%1,%2,%3}, [%4];" \
                 : "=r"(r0), "=r"(r1), "=r"(r2), "=r"(r3) : "r"(addr))

#define MMA16816(c0, c1, c2, c3, a0, a1, a2, a3, b0, b1) \
    asm volatile("mma.sync.aligned.m16n8k16.row.col.f32.bf16.bf16.f32 " \
                 "{%0,%1,%2,%3}, {%4,%5,%6,%7}, {%8,%9}, {%0,%1,%2,%3};" \
                 : "+f"(c0), "+f"(c1), "+f"(c2), "+f"(c3) \
                 : "r"(a0), "r"(a1), "r"(a2), "r"(a3), "r"(b0), "r"(b1))

// packed fp32x2 (Blackwell base ISA, PTX 8.6+)
#define FMA2(acc, a, b) \
    asm("fma.rn.f32x2 %0, %1, %2, %0;" : "+l"(acc) : "l"(a), "l"(b))
#define MUL2(acc, b) \
    asm("mul.rn.f32x2 %0, %0, %1;" : "+l"(acc) : "l"(b))
__device__ __forceinline__ unsigned long long pack2(float v) {
    unsigned long long r; unsigned u = __float_as_uint(v);
    asm("mov.b64 %0, {%1, %1};" : "=l"(r) : "r"(u));
    return r;
}
__device__ __forceinline__ float pk_lo(unsigned long long v) {
    return __uint_as_float((unsigned)(v & 0xffffffffull));
}
__device__ __forceinline__ float pk_hi(unsigned long long v) {
    return __uint_as_float((unsigned)(v >> 32));
}
#define D2L(x) __double_as_longlong(x)

// ---------------- scratch (device globals) ----------
__device__ float g_QKV[(size_t)MM * NQKV];
__device__ __nv_bfloat16 g_xb   [(size_t)MM   * 3 * DIN ];
__device__ __nv_bfloat16 g_Wqkvb[(size_t)NQKV * 3 * DIN ];
__device__ __nv_bfloat16 g_Wob  [(size_t)DOUT * 3 * DOUT];
__device__ __nv_bfloat16 g_ctxb [(size_t)MM   * 3 * DOUT];

// ============================================================================
// fp32 -> 3-segment bf16 split.  mode 0: [h|h|l]  mode 1: [h|l|h]
// ============================================================================
__global__ void split3_kernel(const float* __restrict__ in,
                              __nv_bfloat16* __restrict__ out,
                              int C, size_t total, int mode)
{
    size_t idx = (size_t)blockIdx.x * blockDim.x + threadIdx.x;
    if (idx >= total) return;
    size_t r = idx / (size_t)C;
    int    c = (int)(idx - r * C);
    float v = in[idx];
    __nv_bfloat16 h = __float2bfloat16(v);
    __nv_bfloat16 l = __float2bfloat16(v - __bfloat162float(h));
    __nv_bfloat16* o = out + r * (size_t)(3 * C);
    if (mode == 0) { o[c] = h; o[C + c] = h; o[2 * C + c] = l; }
    else           { o[c] = h; o[C + c] = l; o[2 * C + c] = h; }
}

// ============================================================================
// HMMA bf16 GEMM:  C[M,N] = A[M,K] * B[N,K]^T
// 128x128 CTA tile, BK=64, 4 warps (2x2), warp tile 64x64,
// 3-stage cp.async pipeline (halves barrier count vs BK=32), 2 CTAs/SM.
// smem row stride = 144 B (9 16B-chunks; 9r mod 8 = r -> conflict-free ldsm).
// ============================================================================
#define ROWB   144
#define TILEB  (128 * ROWB)          // 18432 B per operand tile
#define STAGEB (2 * TILEB)           // 36864 B per stage
#define NSTAGE 3
#define GSMEM  (NSTAGE * STAGEB)     // 110592 B (x2 CTAs = 221184 <= 227328)

__global__ __launch_bounds__(128, 2) void gemm_hmma_kernel(
    const __nv_bfloat16* __restrict__ A, const __nv_bfloat16* __restrict__ B,
    float* __restrict__ C, int M, int N, int K)
{
    extern __shared__ __align__(1024) uint8_t sm_[];

    const int tid = threadIdx.x;
    const int wid = tid >> 5;
    const int l   = tid & 31;
    const int warp_m = wid >> 1;         // 0..1
    const int warp_n = wid & 1;          // 0..1

    // CTA swizzle: group 8 M-tiles per N column for L2 reuse of B
    int tm, tn;
    {
        int lin  = blockIdx.y * gridDim.x + blockIdx.x;
        int gsz  = 8 * gridDim.x;
        int gid  = lin / gsz;
        int rem  = lin - gid * gsz;
        int m0   = gid * 8;
        int msz  = min(8, (int)gridDim.y - m0);
        tm = m0 + rem % msz;
        tn = rem / msz;
    }
    const size_t row0 = (size_t)tm * 128;
    const size_t col0 = (size_t)tn * 128;

    const uint32_t sb = smem_to_u32(sm_);

    float acc[4][8][4];
#pragma unroll
    for (int i = 0; i < 4; i++)
#pragma unroll
        for (int j = 0; j < 8; j++)
#pragma unroll
            for (int q = 0; q < 4; q++) acc[i][j][q] = 0.f;

    const int nk = K >> 6;               // BK = 64 elements = 128 B/row

    // staging: tile = 128 rows x 8 chunks(16B). 1024 chunks / 128 thr = 8 each.
    // i = tid + u*128: r = i>>3 covers rows, c = i&7 chunk. 8 threads/row ->
    // 128B contiguous per row group -> coalesced.
#define ISSUE_TILE(stg, t) do {                                                 \
    uint32_t ab = sb + (stg) * STAGEB;                                          \
    uint32_t bb = ab + TILEB;                                                   \
    _Pragma("unroll")                                                           \
    for (int u = 0; u < 8; u++) {                                               \
        int i = tid + u * 128;                                                  \
        int r = i >> 3;                                                         \
        int c = i & 7;                                                          \
        uint32_t so = (uint32_t)(r * ROWB + c * 16);                            \
        CP_ASYNC16(ab + so,                                                     \
                   A + (row0 + r) * (size_t)K + (size_t)(t) * 64 + c * 8);      \
        CP_ASYNC16(bb + so,                                                     \
                   B + (col0 + r) * (size_t)K + (size_t)(t) * 64 + c * 8);      \
    } } while (0)

    // prologue: fill NSTAGE-1 stages
#pragma unroll
    for (int s = 0; s < NSTAGE - 1; s++) {
        if (s < nk) ISSUE_TILE(s, s);
        CP_COMMIT();
    }

    // lane-derived ldmatrix address components (verified mapping)
    const int aRow = warp_m * 64 + (l & 15);                       // + i*16
    const int aKof = (l >> 4) * 16;                                // bytes
    const int bRow = warp_n * 64 + ((l >> 4) & 1) * 8 + (l & 7);   // + j2*16
    const int bKof = ((l >> 3) & 1) * 16;                          // bytes

    int stg = 0;
    for (int t = 0; t < nk; t++) {
        const uint32_t Ab = sb + stg * STAGEB;
        const uint32_t Bb = Ab + TILEB;

        CP_WAIT(NSTAGE - 2);          // tile t resident
        __syncthreads();              // all warps done with the slot we refill

        {   // refill the slot freed last iteration
            int tf = t + NSTAGE - 1;
            if (tf < nk) {
                int sf = stg + NSTAGE - 1;
                if (sf >= NSTAGE) sf -= NSTAGE;
                ISSUE_TILE(sf, tf);
            }
            CP_COMMIT();
        }

        // ---- compute tile t: 4 k-steps of 16, single-buffered fragments ----
#pragma unroll
        for (int ks = 0; ks < 4; ks++) {
            uint32_t af[4][4], bf[8][2];
#pragma unroll
            for (int i = 0; i < 4; i++) {
                uint32_t ad = Ab + (uint32_t)((aRow + i * 16) * ROWB + ks * 32 + aKof);
                LDSM4(af[i][0], af[i][1], af[i][2], af[i][3], ad);
            }
#pragma unroll
            for (int j2 = 0; j2 < 4; j2++) {
                uint32_t bd = Bb + (uint32_t)((bRow + j2 * 16) * ROWB + ks * 32 + bKof);
                LDSM4(bf[2 * j2][0], bf[2 * j2][1], bf[2 * j2 + 1][0], bf[2 * j2 + 1][1], bd);
            }
#pragma unroll
            for (int i = 0; i < 4; i++)
#pragma unroll
                for (int j = 0; j < 8; j++)
                    MMA16816(acc[i][j][0], acc[i][j][1], acc[i][j][2], acc[i][j][3],
                             af[i][0], af[i][1], af[i][2], af[i][3],
                             bf[j][0], bf[j][1]);
        }
        if (++stg == NSTAGE) stg = 0;
    }
#undef ISSUE_TILE

    // epilogue
    const int erow = (int)row0 + warp_m * 64 + (l >> 2);
    const int ecol = (int)col0 + warp_n * 64 + (l & 3) * 2;
#pragma unroll
    for (int i = 0; i < 4; i++) {
#pragma unroll
        for (int j = 0; j < 8; j++) {
            float* p0 = C + (size_t)(erow + i * 16)     * N + ecol + j * 8;
            float* p1 = C + (size_t)(erow + i * 16 + 8) * N + ecol + j * 8;
            *(float2*)p0 = make_float2(acc[i][j][0], acc[i][j][1]);
            *(float2*)p1 = make_float2(acc[i][j][2], acc[i][j][3]);
        }
    }
}

// ============================================================================
// RoPE (in place) on fused QKV buffer.
// ============================================================================
__global__ void rope_fused_kernel(float* __restrict__ QKV)
{
    size_t idx = (size_t)blockIdx.x * blockDim.x + threadIdx.x;
    size_t total = (size_t)BB * SS * (NH + NKV) * 64;
    if (idx >= total) return;

    int   i  = (int)(idx & 63);
    size_t t = idx >> 6;
    int   hh = (int)(t % (NH + NKV));
    size_t bs = t / (NH + NKV);
    int   s  = (int)(bs % SS);

    int coff = (hh < NH) ? hh * HD : KOFF + (hh - NH) * HD;
    float* p = QKV + bs * (size_t)NQKV + coff;

    float inv = 1.0f / powf(10000.0f, (float)(2 * i) / 128.0f);
    float ang = (float)s * inv;
    float sn, cs;
    sincosf(ang, &sn, &cs);

    float x1 = p[i];
    float x2 = p[i + 64];
    p[i]      = x1 * cs - x2 * sn;
    p[i + 64] = x2 * cs + x1 * sn;
}

// ============================================================================
// Causal flash attention (fp32, online softmax), register-blocked, f32x2.
// Epilogue writes 3-segment bf16 ctxb directly (mode 0: [h|h|l]) — the
// Wo-GEMM input — eliminating the separate ctx split3 pass.
// ============================================================================
#define SROW 36
#define ASMEM 77568

__global__ __launch_bounds__(256) void attn_kernel(
    const float* __restrict__ QKV, __nv_bfloat16* __restrict__ ctxb)
{
    extern __shared__ float sm[];
    float* Qs  = sm;
    float* Ks  = Qs + 64 * 132;
    float* Vs  = Ks + 32 * 132;
    float* Ssm = Vs + 32 * 132;
    float* msh = Ssm + 64 * SROW;
    float* lsh = msh + 64;
    float* ash = lsh + 64;

    const int q0  = blockIdx.x * 64;
    const int h   = blockIdx.y;
    const int b   = blockIdx.z;
    const int g   = h / GS;
    const int tid = threadIdx.x;

    const int sr0 = (tid >> 4) * 4;
    const int sc0 = (tid & 15) * 2;
    const int xrow = tid >> 2;
    const int xq   = tid & 3;
    const int pr0 = (tid >> 3) * 2;
    const int pc0 = (tid & 7) * 16;

    const float* Qb = QKV + ((size_t)(b * SS + q0)) * NQKV + (size_t)h * HD;
#pragma unroll
    for (int u = 0; u < 8; u++) {
        int i  = tid + u * 256;
        int r  = i >> 5;
        int c4 = i & 31;
        ((float4*)(Qs + r * 132))[c4] = ((const float4*)(Qb + (size_t)r * NQKV))[c4];
    }
    if (tid < 64) { msh[tid] = -1e30f; lsh[tid] = 0.f; }

    unsigned long long o_pk[2][8];
#pragma unroll
    for (int r = 0; r < 2; r++)
#pragma unroll
        for (int c = 0; c < 8; c++) o_pk[r][c] = 0ull;

    const float scale = 0.08838834764831845f;
    const int kmax = q0 + 64;

    for (int j0 = 0; j0 < kmax; j0 += 32) {
        __syncthreads();

        const float* Kb = QKV + ((size_t)(b * SS + j0)) * NQKV + KOFF + (size_t)g * HD;
        const float* Vb = QKV + ((size_t)(b * SS + j0)) * NQKV + VOFF + (size_t)g * HD;
#pragma unroll
        for (int u = 0; u < 4; u++) {
            int i  = tid + u * 256;
            int r  = i >> 5;
            int c4 = i & 31;
            ((float4*)(Ks + r * 132))[c4] = ((const float4*)(Kb + (size_t)r * NQKV))[c4];
            ((float4*)(Vs + r * 132))[c4] = ((const float4*)(Vb + (size_t)r * NQKV))[c4];
        }
        __syncthreads();

        {
            unsigned long long s_pk[4][2];
#pragma unroll
            for (int r = 0; r < 4; r++) { s_pk[r][0] = 0ull; s_pk[r][1] = 0ull; }
            const double2* k0p = (const double2*)(Ks + sc0 * 132);
            const double2* k1p = (const double2*)(Ks + (sc0 + 1) * 132);
#pragma unroll
            for (int k4 = 0; k4 < 32; k4++) {
                double2 kv0 = k0p[k4];
                double2 kv1 = k1p[k4];
                unsigned long long k0a = D2L(kv0.x), k0b = D2L(kv0.y);
                unsigned long long k1a = D2L(kv1.x), k1b = D2L(kv1.y);
#pragma unroll
                for (int r = 0; r < 4; r++) {
                    double2 qv = ((const double2*)(Qs + (sr0 + r) * 132))[k4];
                    unsigned long long qa = D2L(qv.x), qb = D2L(qv.y);
                    FMA2(s_pk[r][0], qa, k0a);
                    FMA2(s_pk[r][0], qb, k0b);
                    FMA2(s_pk[r][1], qa, k1a);
                    FMA2(s_pk[r][1], qb, k1b);
                }
            }
            const bool diag = (j0 + 31 > q0);
#pragma unroll
            for (int r = 0; r < 4; r++) {
#pragma unroll
                for (int c = 0; c < 2; c++) {
                    float v = (pk_lo(s_pk[r][c]) + pk_hi(s_pk[r][c])) * scale;
                    if (diag && (j0 + sc0 + c > q0 + sr0 + r)) v = -1e30f;
                    Ssm[(sr0 + r) * SROW + sc0 + c] = v;
                }
            }
        }
        __syncthreads();

        {
            float* srow = Ssm + xrow * SROW + xq * 8;
            float mt = -1e30f;
#pragma unroll
            for (int jj = 0; jj < 8; jj++) mt = fmaxf(mt, srow[jj]);
            mt = fmaxf(mt, __shfl_xor_sync(0xffffffffu, mt, 1));
            mt = fmaxf(mt, __shfl_xor_sync(0xffffffffu, mt, 2));
            float m_old = msh[xrow];
            float m_new = fmaxf(m_old, mt);
            float alpha = expf(m_old - m_new);
            float lsum = 0.f;
#pragma unroll
            for (int jj = 0; jj < 8; jj++) {
                float p = expf(srow[jj] - m_new);
                srow[jj] = p;
                lsum += p;
            }
            lsum += __shfl_xor_sync(0xffffffffu, lsum, 1);
            lsum += __shfl_xor_sync(0xffffffffu, lsum, 2);
            if (xq == 0) {
                msh[xrow] = m_new;
                lsh[xrow] = lsh[xrow] * alpha + lsum;
                ash[xrow] = alpha;
            }
        }
        __syncthreads();

        {
            unsigned long long apk0 = pack2(ash[pr0]);
            unsigned long long apk1 = pack2(ash[pr0 + 1]);
#pragma unroll
            for (int c = 0; c < 8; c++) {
                MUL2(o_pk[0][c], apk0);
                MUL2(o_pk[1][c], apk1);
            }
            const float* p0r = Ssm + pr0 * SROW;
            const float* p1r = Ssm + (pr0 + 1) * SROW;
#pragma unroll
            for (int j = 0; j < 32; j++) {
                unsigned long long ppk0 = pack2(p0r[j]);
                unsigned long long ppk1 = pack2(p1r[j]);
                const double2* vp = (const double2*)(Vs + j * 132 + pc0);
#pragma unroll
                for (int c = 0; c < 4; c++) {
                    double2 vv = vp[c];
                    unsigned long long va = D2L(vv.x), vb = D2L(vv.y);
                    FMA2(o_pk[0][2 * c],     ppk0, va);
                    FMA2(o_pk[0][2 * c + 1], ppk0, vb);
                    FMA2(o_pk[1][2 * c],     ppk1, va);
                    FMA2(o_pk[1][2 * c + 1], ppk1, vb);
                }
            }
        }
    }

    // epilogue: normalize + 3-segment bf16 split (mode 0: [h|h|l]) into ctxb.
    // pairs of adjacent cols packed as bf16x2 (4B stores).
#pragma unroll
    for (int r = 0; r < 2; r++) {
        float inv_l = 1.f / lsh[pr0 + r];
        size_t rowb = (size_t)(b * SS + q0 + pr0 + r) * (3 * DOUT);
        int col = h * HD + pc0;
        __nv_bfloat162* oh = (__nv_bfloat162*)(ctxb + rowb + col);
        __nv_bfloat162* oh2= (__nv_bfloat162*)(ctxb + rowb + DOUT + col);
        __nv_bfloat162* ol = (__nv_bfloat162*)(ctxb + rowb + 2 * DOUT + col);
#pragma unroll
        for (int c = 0; c < 8; c++) {
            float v0 = pk_lo(o_pk[r][c]) * inv_l;
            float v1 = pk_hi(o_pk[r][c]) * inv_l;
            __nv_bfloat16 h0 = __float2bfloat16(v0);
            __nv_bfloat16 h1 = __float2bfloat16(v1);
            __nv_bfloat16 l0 = __float2bfloat16(v0 - __bfloat162float(h0));
            __nv_bfloat16 l1 = __float2bfloat16(v1 - __bfloat162float(h1));
            __nv_bfloat162 hp; hp.x = h0; hp.y = h1;
            __nv_bfloat162 lp; lp.x = l0; lp.y = l1;
            oh[c]  = hp;
            oh2[c] = hp;
            ol[c]  = lp;
        }
    }
}

// ============================================================================
// launch
// ============================================================================
extern "C" void kernel_launch(void* const* d_in, const int* in_sizes, int n_in,
                              void* d_out, int out_size)
{
    const float* x  = (const float*)d_in[0];
    const float* Wq = (const float*)d_in[1];
    const float* Wk = (const float*)d_in[2];
    const float* Wv = (const float*)d_in[3];
    const float* Wo = (const float*)d_in[4];
    float* out = (float*)d_out;

    float *QKVp;
    __nv_bfloat16 *xb, *Wqkvb, *Wob, *ctxb;
    cudaGetSymbolAddress((void**)&QKVp, g_QKV);
    cudaGetSymbolAddress((void**)&xb, g_xb);
    cudaGetSymbolAddress((void**)&Wqkvb, g_Wqkvb);
    cudaGetSymbolAddress((void**)&Wob, g_Wob);
    cudaGetSymbolAddress((void**)&ctxb, g_ctxb);

    cudaFuncSetAttribute(attn_kernel,
                         cudaFuncAttributeMaxDynamicSharedMemorySize, ASMEM);
    cudaFuncSetAttribute(gemm_hmma_kernel,
                         cudaFuncAttributeMaxDynamicSharedMemorySize, GSMEM);

    // splits: x, Wq, Wk, Wv, Wo
    size_t t1 = (size_t)MM * DIN;
    split3_kernel<<<(unsigned)((t1 + 255) / 256), 256>>>(x, xb, DIN, t1, 0);
    size_t t2 = (size_t)DOUT * DIN;
    split3_kernel<<<(unsigned)((t2 + 255) / 256), 256>>>(Wq, Wqkvb, DIN, t2, 1);
    size_t t3 = (size_t)(NKV * HD) * DIN;
    split3_kernel<<<(unsigned)((t3 + 255) / 256), 256>>>(
        Wk, Wqkvb + (size_t)KOFF * 3 * DIN, DIN, t3, 1);
    split3_kernel<<<(unsigned)((t3 + 255) / 256), 256>>>(
        Wv, Wqkvb + (size_t)VOFF * 3 * DIN, DIN, t3, 1);
    size_t t4 = (size_t)DOUT * DOUT;
    split3_kernel<<<(unsigned)((t4 + 255) / 256), 256>>>(Wo, Wob, DOUT, t4, 1);

    // fused QKV projection GEMM
    {
        dim3 gq(NQKV / 128, MM / 128);
        gemm_hmma_kernel<<<gq, 128, GSMEM>>>(xb, Wqkvb, QKVp, MM, NQKV, 3 * DIN);
    }

    // RoPE on Q and K heads
    {
        size_t tr = (size_t)BB * SS * (NH + NKV) * 64;
        rope_fused_kernel<<<(unsigned)((tr + 255) / 256), 256>>>(QKVp);
    }

    // attention (writes 3-seg bf16 ctxb directly)
    {
        dim3 ga(SS / 64, NH, BB);
        attn_kernel<<<ga, 256, ASMEM>>>(QKVp, ctxb);
    }

    // output projection -> d_out
    {
        dim3 go(DOUT / 128, MM / 128);
        gemm_hmma_kernel<<<go, 128, GSMEM>>>(ctxb, Wob, out, MM, DOUT, 3 * DOUT);
    }
}